// round 3
// baseline (speedup 1.0000x reference)
#include <cuda_runtime.h>
#include <cstdint>

// Problem constants
#define NB 8
#define RR 256
#define CI 64
#define CO 64
#define MD 16
#define KXN 32  // 16 top + 16 bottom kx modes

typedef unsigned long long u64;

// ---------------------------------------------------------------------------
// Scratch (device globals -- no allocation allowed)
// ---------------------------------------------------------------------------
__device__ float2 g_A[NB * MD * RR * CI];   // [b][ky][u][i]   16.8 MB
__device__ float2 g_F[NB * KXN * MD * CI];  // [b][kx][ky][i]   2.1 MB
__device__ float2 g_G[NB * KXN * MD * CO];  // [b][kx][ky][o]   2.1 MB
__device__ float2 g_H[NB * MD * RR * CO];   // [b][ky][u][o]   16.8 MB

// ---------------------------------------------------------------------------
// Packed f32x2 helpers (Blackwell dual-FP32 pipe; only reachable via PTX)
// ---------------------------------------------------------------------------
__device__ __forceinline__ u64 pack2(float lo, float hi) {
    u64 r;
    asm("mov.b64 %0, {%1,%2};" : "=l"(r) : "f"(lo), "f"(hi));
    return r;
}
__device__ __forceinline__ u64 fma2(u64 a, u64 b, u64 c) {
    u64 r;
    asm("fma.rn.f32x2 %0, %1, %2, %3;" : "=l"(r) : "l"(a), "l"(b), "l"(c));
    return r;
}
__device__ __forceinline__ u64 add2(u64 a, u64 b) {
    u64 r;
    asm("add.rn.f32x2 %0, %1, %2;" : "=l"(r) : "l"(a), "l"(b));
    return r;
}
__device__ __forceinline__ void unpack2(u64 v, float& lo, float& hi) {
    asm("mov.b64 {%0,%1}, %2;" : "=f"(lo), "=f"(hi) : "l"(v));
}

__device__ __forceinline__ float silu_f(float x) {
    float e = __expf(-x);
    return __fdividef(x, 1.0f + e);
}

// ---------------------------------------------------------------------------
// K1: partial column DFT along v for ky = 0..15 (packed channel pairs).
// A[b][ky][u][i] = sum_v X[b,u,v,i] * exp(-2*pi*i*ky*v/256)
// v <-> 256-v symmetry; X row staged in shared; dup'd twiddle tables.
// Thread: lane = channel pair, g = tid>>5 -> ky pair {2g, 2g+1}.
// Dynamic shared: xs[8192 u64] (64KB) | csd[256] | snd[256]
// ---------------------------------------------------------------------------
#define K1_XS 0
#define K1_CS 8192
#define K1_SN 8448
#define K1_TOT_U64 8704  // 69632 bytes

__global__ __launch_bounds__(256) void k1_coldft(const float* __restrict__ X) {
    extern __shared__ u64 sm1[];
    u64* xs = sm1 + K1_XS;
    u64* csd = sm1 + K1_CS;
    u64* snd = sm1 + K1_SN;

    int tid = threadIdx.x;
    {
        float s, c;
        sincospif((float)tid * (1.0f / 128.0f), &s, &c);  // angle 2*pi*tid/256
        csd[tid] = pack2(c, c);
        snd[tid] = pack2(-s, -s);
    }
    int u = blockIdx.x, b = blockIdx.y;
    {
        const float4* x4 = (const float4*)(X + ((size_t)(b * RR + u) * RR) * CI);
        float4* xs4 = (float4*)xs;
        for (int p = tid; p < 4096; p += 256) xs4[p] = x4[p];
    }
    __syncthreads();

    int lane = tid & 31, g = tid >> 5;
    int ky0 = 2 * g, ky1 = 2 * g + 1;

    u64 one = pack2(1.0f, 1.0f), mone = pack2(-1.0f, -1.0f);
    u64 x0 = xs[lane];
    u64 x128 = xs[128 * 32 + lane];
    u64 ar0 = fma2(x128, one, x0);   // ky even: x0 + x128
    u64 ar1 = fma2(x128, mone, x0);  // ky odd:  x0 - x128
    u64 ai0 = pack2(0.0f, 0.0f), ai1 = ai0;

    int t0 = 0, t1 = 0;
#pragma unroll 2
    for (int v = 1; v <= 127; ++v) {
        u64 xa = xs[v * 32 + lane];
        u64 xb = xs[(256 - v) * 32 + lane];
        u64 smv = fma2(xb, one, xa);
        u64 dfv = fma2(xb, mone, xa);
        t0 = (t0 + ky0) & 255;  // ky0*v
        t1 = (t1 + ky1) & 255;  // ky1*v
        ar0 = fma2(smv, csd[t0], ar0);
        ai0 = fma2(dfv, snd[t0], ai0);
        ar1 = fma2(smv, csd[t1], ar1);
        ai1 = fma2(dfv, snd[t1], ai1);
    }

    float4* a4 = (float4*)g_A;
    float rl, rh, il, ih;
    unpack2(ar0, rl, rh); unpack2(ai0, il, ih);
    a4[((size_t)(b * MD + ky0) * RR + u) * 32 + lane] = make_float4(rl, il, rh, ih);
    unpack2(ar1, rl, rh); unpack2(ai1, il, ih);
    a4[((size_t)(b * MD + ky1) * RR + u) * 32 + lane] = make_float4(rl, il, rh, ih);
}

// ---------------------------------------------------------------------------
// K2: partial row DFT along u for kx in {0..15, 240..255} (packed complex).
// F[b][kxidx][ky][i] = sum_u A[b,ky,u,i] * exp(-2*pi*i*kx*u/256)
// z-split over kx halves (256 blocks); per thread 4 modes.
// ---------------------------------------------------------------------------
__global__ __launch_bounds__(256) void k2_rowdft() {
    __shared__ u64 csd[256];  // (c, c)
    __shared__ u64 ssd[256];  // (s, s)
    int tid = threadIdx.x;
    {
        float s, c;
        sincospif((float)tid * (1.0f / 128.0f), &s, &c);
        csd[tid] = pack2(c, c);
        ssd[tid] = pack2(s, s);
    }
    __syncthreads();

    int ky = blockIdx.x, b = blockIdx.y, z = blockIdx.z;
    int i = tid & 63, g = tid >> 6;  // g in 0..3 -> 4 modes
    int m0 = z * 16 + g * 4;         // kxidx base for this thread
    const u64* ap = (const u64*)(g_A + ((size_t)(b * MD + ky) * RR) * CI) + i;

    u64 one = pack2(1.0f, 1.0f), mone = pack2(-1.0f, -1.0f);
    u64 A0 = ap[0];
    u64 A128 = ap[128 * CI];

    u64 FP[4];
    int kxv[4], tt[4];
#pragma unroll
    for (int m = 0; m < 4; m++) {
        int idx = m0 + m;
        int kx = (idx < 16) ? idx : (224 + idx);
        kxv[m] = kx;
        tt[m] = 0;
        FP[m] = fma2(A128, (idx & 1) ? mone : one, A0);
    }

#pragma unroll 2
    for (int uu = 1; uu <= 127; ++uu) {
        u64 aa = ap[uu * CI];
        u64 ab = ap[(256 - uu) * CI];
        u64 P1 = add2(aa, ab);            // (prs, pis)
        u64 D = fma2(ab, mone, aa);       // (mrs, mis)
        float mrs, mis;
        unpack2(D, mrs, mis);
        u64 P2 = pack2(mis, -mrs);        // (mis, -mrs)
#pragma unroll
        for (int m = 0; m < 4; m++) {
            tt[m] = (tt[m] + kxv[m]) & 255;  // kx*uu
            FP[m] = fma2(P1, csd[tt[m]], FP[m]);
            FP[m] = fma2(P2, ssd[tt[m]], FP[m]);
        }
    }

#pragma unroll
    for (int m = 0; m < 4; m++) {
        float fr, fi;
        unpack2(FP[m], fr, fi);
        g_F[(((size_t)(b * KXN + m0 + m) * MD) + ky) * CI + i] = make_float2(fr, fi);
    }
}

// ---------------------------------------------------------------------------
// K3: channel mix (complex einsum over input channels) + ortho-norm fold.
// G[b][kxidx][ky][o] = (1/65536) * sum_i F[b][kxidx][ky][i] * W[i][o]
// ---------------------------------------------------------------------------
__global__ __launch_bounds__(256) void k3_mix(const float* __restrict__ fw0,
                                              const float* __restrict__ fw1) {
    __shared__ float2 ws[CI * CO];   // 32 KB
    __shared__ float2 fs[NB][CI];    // 4 KB
    int tid = threadIdx.x;
    int kxi = blockIdx.x, ky = blockIdx.y;
    const float* src = (kxi < 16) ? fw0 : fw1;
    int x = (kxi < 16) ? kxi : (kxi - 16);

    for (int p = tid; p < CI * CO; p += 256) {
        int i = p >> 6, o = p & 63;
        ws[p] = *(const float2*)(src + ((((size_t)i * CO + o) * MD + x) * MD + ky) * 2);
    }
    for (int p = tid; p < NB * CI; p += 256) {
        int bb = p >> 6, i = p & 63;
        fs[bb][i] = g_F[(((size_t)(bb * KXN + kxi) * MD) + ky) * CI + i];
    }
    __syncthreads();

    int o = tid & 63, bg = tid >> 6;
    const float scale = 1.0f / 65536.0f;  // ortho norm (1/256 fwd * 1/256 inv)
    for (int bb = bg; bb < NB; bb += 4) {
        float Gr = 0.f, Gi = 0.f;
#pragma unroll 8
        for (int i = 0; i < CI; i++) {
            float2 f = fs[bb][i];
            float2 w = ws[i * CO + o];
            Gr += f.x * w.x - f.y * w.y;
            Gi += f.x * w.y + f.y * w.x;
        }
        g_G[(((size_t)(bb * KXN + kxi) * MD) + ky) * CO + o] =
            make_float2(Gr * scale, Gi * scale);
    }
}

// ---------------------------------------------------------------------------
// K4: inverse DFT along kx (32 modes -> 256 u), packed (Hr,Hi).
// H[b][ky][u][o] = sum_kxidx G[b][kxidx][ky][o] * exp(+2*pi*i*kx*u/256)
// z-split over u quarters (512 blocks); 16 u per thread, mode-outer loop.
// ---------------------------------------------------------------------------
__global__ __launch_bounds__(256) void k4_invrow() {
    __shared__ u64 twc[256];       // (c, s)
    __shared__ u64 tws[256];       // (-s, c)
    __shared__ u64 gsx[KXN * CO];  // (gx, gx)  16KB
    __shared__ u64 gsy[KXN * CO];  // (gy, gy)  16KB
    int tid = threadIdx.x;
    {
        float s, c;
        sincospif((float)tid * (1.0f / 128.0f), &s, &c);
        twc[tid] = pack2(c, s);
        tws[tid] = pack2(-s, c);
    }
    int ky = blockIdx.x, b = blockIdx.y;
    for (int p = tid; p < KXN * CO; p += 256) {
        float2 g2 = g_G[(((size_t)(b * KXN + (p >> 6)) * MD) + ky) * CO + (p & 63)];
        gsx[p] = pack2(g2.x, g2.x);
        gsy[p] = pack2(g2.y, g2.y);
    }
    __syncthreads();

    int o = tid & 63, ug = tid >> 6;
    int u0 = blockIdx.z * 64 + ug * 16;

    u64 H[16];
#pragma unroll
    for (int q = 0; q < 16; q++) H[q] = pack2(0.0f, 0.0f);

#pragma unroll 4
    for (int idx = 0; idx < KXN; idx++) {
        int kx = (idx < 16) ? idx : (224 + idx);
        u64 gx = gsx[idx * CO + o];
        u64 gy = gsy[idx * CO + o];
        int t = (kx * u0) & 255;
#pragma unroll
        for (int q = 0; q < 16; q++) {
            H[q] = fma2(gx, twc[t], H[q]);
            H[q] = fma2(gy, tws[t], H[q]);
            t = (t + kx) & 255;
        }
    }

    float2* hp = g_H + (((size_t)(b * MD + ky) * RR) + u0) * CO + o;
#pragma unroll
    for (int q = 0; q < 16; q++) {
        float hr, hi;
        unpack2(H[q], hr, hi);
        hp[q * CO] = make_float2(hr, hi);
    }
}

// ---------------------------------------------------------------------------
// K5: fused inverse real-DFT along ky (Hermitian, irfft semantics) +
// residual GEMM (X @ W_res + b_res) + SiLU. Packed f32x2, 8v x 8o tiles.
// Shared (u64 units): Xpair[128*67] | Hrd[1024] | Hid[1024] | (floats:)
//   cs2[256] ns2[256] Ws[4096] br[64]
// ---------------------------------------------------------------------------
#define XP_OFF 0
#define XP_STRIDE 67
#define HRD_OFF (XP_OFF + 128 * XP_STRIDE)   // 8576
#define HID_OFF (HRD_OFF + MD * CO)          // 9600
#define F_BASE ((HID_OFF + MD * CO) * 2)     // float index 21248
#define CS_F F_BASE
#define NS_F (CS_F + 256)
#define WS_F (NS_F + 256)
#define BR_F (WS_F + 4096)
#define K5_TOT_BYTES ((BR_F + 64) * 4)       // 103,168 bytes

__global__ __launch_bounds__(256, 2) void k5_final(const float* __restrict__ X,
                                                   const float* __restrict__ Wres,
                                                   const float* __restrict__ bres,
                                                   float* __restrict__ out) {
    extern __shared__ u64 sm5[];
    u64* Xp = sm5 + XP_OFF;
    u64* Hrd = sm5 + HRD_OFF;
    u64* Hid = sm5 + HID_OFF;
    float* smf = (float*)sm5;
    float* cs2 = smf + CS_F;
    float* ns2 = smf + NS_F;
    float* Ws = smf + WS_F;
    float* br = smf + BR_F;

    int tid = threadIdx.x;
    int u = blockIdx.x, b = blockIdx.y;

    {
        float s, c;
        sincospif((float)tid * (1.0f / 128.0f), &s, &c);
        cs2[tid] = 2.0f * c;   // factor 2 folded (Hermitian pairs)
        ns2[tid] = -2.0f * s;
    }
    if (tid < 64) br[tid] = bres[tid];
    {
        const float4* w4 = (const float4*)Wres;
        float4* ws4 = (float4*)Ws;
        for (int p = tid; p < 1024; p += 256) ws4[p] = w4[p];
    }
    {
        const float4* x4 = (const float4*)(X + ((size_t)(b * RR + u) * RR) * CI);
        for (int p = tid; p < 4096; p += 256) {
            float4 xv = x4[p];
            int v = p >> 4;
            int cq = (p & 15) * 4;
            float* base = (float*)(Xp + (v >> 1) * XP_STRIDE + cq) + (v & 1);
            base[0] = xv.x; base[2] = xv.y; base[4] = xv.z; base[6] = xv.w;
        }
    }
    for (int p = tid; p < MD * CO; p += 256) {
        float2 h = g_H[(((size_t)(b * MD + (p >> 6)) * RR) + u) * CO + (p & 63)];
        Hrd[p] = pack2(h.x, h.x);
        Hid[p] = pack2(h.y, h.y);
    }
    __syncthreads();

    int vg = tid >> 3, og = tid & 7;
    int v0 = vg * 8, o0 = og * 8;
    int vp0 = vg * 4;

    u64 acc[4][8];
#pragma unroll
    for (int k = 0; k < 8; k++) {
        u64 bb = pack2(br[o0 + k], br[o0 + k]);
#pragma unroll
        for (int p = 0; p < 4; p++) acc[p][k] = bb;
    }

    // Residual GEMM: acc[p][k] over v-pair vp0+p x o (o0+k)
#pragma unroll 4
    for (int c = 0; c < CI; c++) {
        u64 xp0 = Xp[(vp0 + 0) * XP_STRIDE + c];
        u64 xp1 = Xp[(vp0 + 1) * XP_STRIDE + c];
        u64 xp2 = Xp[(vp0 + 2) * XP_STRIDE + c];
        u64 xp3 = Xp[(vp0 + 3) * XP_STRIDE + c];
        const float* wr = Ws + c * 64 + o0;
        float4 wa = *(const float4*)wr;
        float4 wb = *(const float4*)(wr + 4);
        float wv[8] = {wa.x, wa.y, wa.z, wa.w, wb.x, wb.y, wb.z, wb.w};
#pragma unroll
        for (int k = 0; k < 8; k++) {
            u64 wd = pack2(wv[k], wv[k]);
            acc[0][k] = fma2(xp0, wd, acc[0][k]);
            acc[1][k] = fma2(xp1, wd, acc[1][k]);
            acc[2][k] = fma2(xp2, wd, acc[2][k]);
            acc[3][k] = fma2(xp3, wd, acc[3][k]);
        }
    }

    // Spectral ky = 0 term: + Re(H0[o]) (DC imag discarded, matches irfft)
#pragma unroll
    for (int k = 0; k < 8; k++) {
        u64 h0 = Hrd[o0 + k];
#pragma unroll
        for (int p = 0; p < 4; p++) acc[p][k] = add2(acc[p][k], h0);
    }

    // Spectral ky = 1..15: + 2*(Hr*cos - Hi*sin)
    for (int ky = 1; ky < MD; ky++) {
        u64 cp[4], sp[4];
#pragma unroll
        for (int p = 0; p < 4; p++) {
            int ta = (ky * (v0 + 2 * p)) & 255;
            int tb = (ta + ky) & 255;
            cp[p] = pack2(cs2[ta], cs2[tb]);
            sp[p] = pack2(ns2[ta], ns2[tb]);
        }
        const u64* hrp = Hrd + ky * 64 + o0;
        const u64* hip = Hid + ky * 64 + o0;
#pragma unroll
        for (int k = 0; k < 8; k++) {
            u64 hrd = hrp[k];
            u64 hid = hip[k];
#pragma unroll
            for (int p = 0; p < 4; p++) {
                acc[p][k] = fma2(hrd, cp[p], acc[p][k]);
                acc[p][k] = fma2(hid, sp[p], acc[p][k]);
            }
        }
    }

    // SiLU + store (float4)
    float* ob = out + (((size_t)(b * RR + u) * RR) + v0) * CO + o0;
#pragma unroll
    for (int p = 0; p < 4; p++) {
        float lo[8], hi[8];
#pragma unroll
        for (int k = 0; k < 8; k++) unpack2(acc[p][k], lo[k], hi[k]);
        float* r0 = ob + (size_t)(2 * p) * CO;
        float* r1 = ob + (size_t)(2 * p + 1) * CO;
        *(float4*)r0 = make_float4(silu_f(lo[0]), silu_f(lo[1]), silu_f(lo[2]), silu_f(lo[3]));
        *(float4*)(r0 + 4) = make_float4(silu_f(lo[4]), silu_f(lo[5]), silu_f(lo[6]), silu_f(lo[7]));
        *(float4*)r1 = make_float4(silu_f(hi[0]), silu_f(hi[1]), silu_f(hi[2]), silu_f(hi[3]));
        *(float4*)(r1 + 4) = make_float4(silu_f(hi[4]), silu_f(hi[5]), silu_f(hi[6]), silu_f(hi[7]));
    }
}

// ---------------------------------------------------------------------------
// Launcher
// ---------------------------------------------------------------------------
extern "C" void kernel_launch(void* const* d_in, const int* in_sizes, int n_in,
                              void* d_out, int out_size) {
    const float* X = (const float*)d_in[0];
    const float* Wres = (const float*)d_in[1];
    const float* bres = (const float*)d_in[2];
    const float* fw0 = (const float*)d_in[3];
    const float* fw1 = (const float*)d_in[4];
    float* out = (float*)d_out;

    cudaFuncSetAttribute(k1_coldft, cudaFuncAttributeMaxDynamicSharedMemorySize,
                         K1_TOT_U64 * 8);
    cudaFuncSetAttribute(k5_final, cudaFuncAttributeMaxDynamicSharedMemorySize,
                         K5_TOT_BYTES);

    k1_coldft<<<dim3(RR, NB), 256, K1_TOT_U64 * 8>>>(X);
    k2_rowdft<<<dim3(MD, NB, 2), 256>>>();
    k3_mix<<<dim3(KXN, MD), 256>>>(fw0, fw1);
    k4_invrow<<<dim3(MD, NB, 4), 256>>>();
    k5_final<<<dim3(RR, NB), 256, K5_TOT_BYTES>>>(X, Wres, bres, out);
}

// round 4
// speedup vs baseline: 1.1940x; 1.1940x over previous
#include <cuda_runtime.h>
#include <cstdint>

// Problem constants
#define NB 8
#define RR 256
#define CI 64
#define CO 64
#define MD 16
#define KXN 32  // 16 top + 16 bottom kx modes

// ---------------------------------------------------------------------------
// Scratch (device globals -- no allocation allowed)
// ---------------------------------------------------------------------------
__device__ float2 g_A[NB * MD * RR * CI];   // [b][ky][u][i]   16.8 MB
__device__ float2 g_F[NB * KXN * MD * CI];  // [b][kx][ky][i]   2.1 MB
__device__ float2 g_G[NB * KXN * MD * CO];  // [b][kx][ky][o]   2.1 MB
__device__ float2 g_H[NB * MD * RR * CO];   // [b][ky][u][o]   16.8 MB

// ---------------------------------------------------------------------------
// Packed f32x2 helpers (Blackwell dual-FP32 pipe; only reachable via PTX)
// ---------------------------------------------------------------------------
__device__ __forceinline__ unsigned long long pack2(float lo, float hi) {
    unsigned long long r;
    asm("mov.b64 %0, {%1,%2};" : "=l"(r) : "f"(lo), "f"(hi));
    return r;
}
__device__ __forceinline__ unsigned long long fma2(unsigned long long a,
                                                   unsigned long long b,
                                                   unsigned long long c) {
    unsigned long long r;
    asm("fma.rn.f32x2 %0, %1, %2, %3;" : "=l"(r) : "l"(a), "l"(b), "l"(c));
    return r;
}
__device__ __forceinline__ unsigned long long add2(unsigned long long a,
                                                   unsigned long long b) {
    unsigned long long r;
    asm("add.rn.f32x2 %0, %1, %2;" : "=l"(r) : "l"(a), "l"(b));
    return r;
}
__device__ __forceinline__ void unpack2(unsigned long long v, float& lo, float& hi) {
    asm("mov.b64 {%0,%1}, %2;" : "=f"(lo), "=f"(hi) : "l"(v));
}

__device__ __forceinline__ float silu_f(float x) {
    float e = __expf(-x);
    return __fdividef(x, 1.0f + e);
}

// ---------------------------------------------------------------------------
// K1: partial column DFT along v for ky = 0..15.
// A[b][ky][u][i] = sum_v X[b,u,v,i] * exp(-2*pi*i*ky*v/256)
// Uses v <-> 256-v symmetry: shared sum/diff across all ky.
// (R1 formulation; unroll raised to 4 for more load MLP.)
// ---------------------------------------------------------------------------
__global__ __launch_bounds__(256) void k1_coldft(const float* __restrict__ X) {
    __shared__ float cs[256], sn[256];
    int tid = threadIdx.x;
    {
        float s, c;
        sincospif((float)tid * (1.0f / 128.0f), &s, &c);  // angle 2*pi*tid/256
        cs[tid] = c;
        sn[tid] = s;
    }
    __syncthreads();

    int u = blockIdx.x, b = blockIdx.y;
    int i = tid & 63, g = tid >> 6;  // g handles ky = 4g .. 4g+3
    const float* xr = X + ((size_t)(b * RR + u) * RR) * CI + i;

    float x0 = xr[0];
    float x128 = xr[128 * CI];
    int kyb = g * 4;  // even -> parities 0,1,0,1
    float ar0 = x0 + x128, ar1 = x0 - x128, ar2 = x0 + x128, ar3 = x0 - x128;
    float ai0 = 0.f, ai1 = 0.f, ai2 = 0.f, ai3 = 0.f;

#pragma unroll 4
    for (int v = 1; v <= 127; ++v) {
        float xa = xr[v * CI];
        float xb = xr[(256 - v) * CI];
        float sm = xa + xb, df = xa - xb;
        int t0 = (kyb * v) & 255;
        int t1 = (t0 + v) & 255;
        int t2 = (t1 + v) & 255;
        int t3 = (t2 + v) & 255;
        ar0 += sm * cs[t0]; ai0 -= df * sn[t0];
        ar1 += sm * cs[t1]; ai1 -= df * sn[t1];
        ar2 += sm * cs[t2]; ai2 -= df * sn[t2];
        ar3 += sm * cs[t3]; ai3 -= df * sn[t3];
    }

    float2* ap = g_A + ((size_t)(b * MD + kyb) * RR + u) * CI + i;
    ap[0 * RR * CI] = make_float2(ar0, ai0);
    ap[1 * RR * CI] = make_float2(ar1, ai1);
    ap[2 * RR * CI] = make_float2(ar2, ai2);
    ap[3 * RR * CI] = make_float2(ar3, ai3);
}

// ---------------------------------------------------------------------------
// K2: partial row DFT along u for kx in {0..15, 240..255}.
// F[b][kxidx][ky][i] = sum_u A[b,ky,u,i] * exp(-2*pi*i*kx*u/256)
// u <-> 256-u symmetry with shared complex sum/diff.
// (R1 math; z-split x2 so each thread handles 4 modes -> 256 blocks.)
// ---------------------------------------------------------------------------
__global__ __launch_bounds__(256) void k2_rowdft() {
    __shared__ float cs[256], sn[256];
    int tid = threadIdx.x;
    {
        float s, c;
        sincospif((float)tid * (1.0f / 128.0f), &s, &c);
        cs[tid] = c;
        sn[tid] = s;
    }
    __syncthreads();

    int ky = blockIdx.x, b = blockIdx.y, z = blockIdx.z;
    int i = tid & 63, g = tid >> 6;     // g in 0..3
    int m0 = z * 16 + g * 4;            // this thread's 4 kxidx values
    const float2* ap = g_A + ((size_t)(b * MD + ky) * RR) * CI + i;

    float Fr[4], Fi[4];
    float2 a0 = ap[0];
    float2 a128 = ap[128 * CI];
    int kxv[4];
#pragma unroll
    for (int m = 0; m < 4; m++) {
        int idx = m0 + m;
        kxv[m] = (idx < 16) ? idx : (224 + idx);  // 240..255
        float sgn = (idx & 1) ? -1.0f : 1.0f;
        Fr[m] = a0.x + sgn * a128.x;
        Fi[m] = a0.y + sgn * a128.y;
    }

#pragma unroll 4
    for (int uu = 1; uu <= 127; ++uu) {
        float2 aa = ap[uu * CI];
        float2 ab = ap[(256 - uu) * CI];
        float prs = aa.x + ab.x, mrs = aa.x - ab.x;
        float pis = aa.y + ab.y, mis = aa.y - ab.y;
#pragma unroll
        for (int m = 0; m < 4; m++) {
            int t = (kxv[m] * uu) & 255;
            float c = cs[t], s = sn[t];
            Fr[m] += prs * c + mis * s;
            Fi[m] += pis * c - mrs * s;
        }
    }

#pragma unroll
    for (int m = 0; m < 4; m++) {
        g_F[(((size_t)(b * KXN + m0 + m) * MD) + ky) * CI + i] = make_float2(Fr[m], Fi[m]);
    }
}

// ---------------------------------------------------------------------------
// K3: channel mix (complex einsum over input channels) + ortho-norm fold.
// G[b][kxidx][ky][o] = (1/65536) * sum_i F[b][kxidx][ky][i] * W[i][o]
// ---------------------------------------------------------------------------
__global__ __launch_bounds__(256) void k3_mix(const float* __restrict__ fw0,
                                              const float* __restrict__ fw1) {
    __shared__ float2 ws[CI * CO];   // 32 KB
    __shared__ float2 fs[NB][CI];    // 4 KB
    int tid = threadIdx.x;
    int kxi = blockIdx.x, ky = blockIdx.y;
    const float* src = (kxi < 16) ? fw0 : fw1;
    int x = (kxi < 16) ? kxi : (kxi - 16);

    for (int p = tid; p < CI * CO; p += 256) {
        int i = p >> 6, o = p & 63;
        ws[p] = *(const float2*)(src + ((((size_t)i * CO + o) * MD + x) * MD + ky) * 2);
    }
    for (int p = tid; p < NB * CI; p += 256) {
        int bb = p >> 6, i = p & 63;
        fs[bb][i] = g_F[(((size_t)(bb * KXN + kxi) * MD) + ky) * CI + i];
    }
    __syncthreads();

    int o = tid & 63, bg = tid >> 6;
    const float scale = 1.0f / 65536.0f;  // ortho norm (1/256 fwd * 1/256 inv)
    for (int bb = bg; bb < NB; bb += 4) {
        float Gr = 0.f, Gi = 0.f;
#pragma unroll 8
        for (int i = 0; i < CI; i++) {
            float2 f = fs[bb][i];
            float2 w = ws[i * CO + o];
            Gr += f.x * w.x - f.y * w.y;
            Gi += f.x * w.y + f.y * w.x;
        }
        g_G[(((size_t)(bb * KXN + kxi) * MD) + ky) * CO + o] =
            make_float2(Gr * scale, Gi * scale);
    }
}

// ---------------------------------------------------------------------------
// K4: inverse DFT along kx (32 modes -> 256 u).
// H[b][ky][u][o] = sum_kxidx G[b][kxidx][ky][o] * exp(+2*pi*i*kx*u/256)
// (R1 math; z-split x4 so each thread handles 16 u -> 512 blocks.)
// ---------------------------------------------------------------------------
__global__ __launch_bounds__(256) void k4_invrow() {
    __shared__ float cs[256], sn[256];
    __shared__ float2 gs[KXN][CO];  // 16 KB
    int tid = threadIdx.x;
    {
        float s, c;
        sincospif((float)tid * (1.0f / 128.0f), &s, &c);
        cs[tid] = c;
        sn[tid] = s;
    }
    int ky = blockIdx.x, b = blockIdx.y;
    for (int p = tid; p < KXN * CO; p += 256) {
        int idx = p >> 6, o = p & 63;
        gs[idx][o] = g_G[(((size_t)(b * KXN + idx) * MD) + ky) * CO + o];
    }
    __syncthreads();

    int o = tid & 63, ug = tid >> 6;
    int ubase = blockIdx.z * 64 + ug * 16;

    for (int uu = 0; uu < 16; ++uu) {
        int u = ubase + uu;
        float Hrv = 0.f, Hiv = 0.f;
        int du = u & 255;
        int t = 0;  // kx = 0..15: t = kx*u mod 256
#pragma unroll
        for (int idx = 0; idx < 16; idx++) {
            float2 g2 = gs[idx][o];
            float c = cs[t], s = sn[t];
            Hrv += g2.x * c - g2.y * s;
            Hiv += g2.x * s + g2.y * c;
            t = (t + du) & 255;
        }
        t = (240 * u) & 255;  // kx = 240..255
#pragma unroll
        for (int idx = 16; idx < 32; idx++) {
            float2 g2 = gs[idx][o];
            float c = cs[t], s = sn[t];
            Hrv += g2.x * c - g2.y * s;
            Hiv += g2.x * s + g2.y * c;
            t = (t + du) & 255;
        }
        g_H[(((size_t)(b * MD + ky) * RR) + u) * CO + o] = make_float2(Hrv, Hiv);
    }
}

// ---------------------------------------------------------------------------
// K5: fused inverse real-DFT along ky (Hermitian, irfft semantics: DC imag
// discarded) + residual GEMM (X @ W_res + b_res) + SiLU.
// Packed f32x2 FMAs; 8v x 8o register tiles per thread. (R1 version.)
// ---------------------------------------------------------------------------
#define SM5_WS 0
#define SM5_XS 4096                      // Xs[v][65] (padded: conflict-free)
#define SM5_HR (SM5_XS + 256 * 65)       // 20736
#define SM5_HI (SM5_HR + MD * CO)
#define SM5_CS (SM5_HI + MD * CO)
#define SM5_NS (SM5_CS + 256)
#define SM5_BR (SM5_NS + 256)
#define SM5_TOT (SM5_BR + 64)            // 23360 floats = 93440 bytes

__global__ __launch_bounds__(256, 2) void k5_final(const float* __restrict__ X,
                                                   const float* __restrict__ Wres,
                                                   const float* __restrict__ bres,
                                                   float* __restrict__ out) {
    extern __shared__ float sm[];
    float* Ws = sm + SM5_WS;
    float* Xs = sm + SM5_XS;
    float* Hr = sm + SM5_HR;
    float* Hi = sm + SM5_HI;
    float* cs2 = sm + SM5_CS;
    float* ns2 = sm + SM5_NS;
    float* br = sm + SM5_BR;

    int tid = threadIdx.x;
    int u = blockIdx.x, b = blockIdx.y;

    {
        float s, c;
        sincospif((float)tid * (1.0f / 128.0f), &s, &c);
        cs2[tid] = 2.0f * c;   // factor 2 folded (Hermitian pairs)
        ns2[tid] = -2.0f * s;
    }
    if (tid < 64) br[tid] = bres[tid];
    {
        const float4* w4 = (const float4*)Wres;
        float4* ws4 = (float4*)Ws;
        for (int p = tid; p < 1024; p += 256) ws4[p] = w4[p];
    }
    {
        const float4* x4 = (const float4*)(X + ((size_t)(b * RR + u) * RR) * CI);
        for (int p = tid; p < 4096; p += 256) {
            float4 xv = x4[p];
            int v = p >> 4;            // 16 float4 per v-row
            int c = (p & 15) * 4;
            float* d = Xs + v * 65 + c;
            d[0] = xv.x; d[1] = xv.y; d[2] = xv.z; d[3] = xv.w;
        }
    }
    for (int p = tid; p < MD * CO; p += 256) {
        int ky = p >> 6, o = p & 63;
        float2 h = g_H[(((size_t)(b * MD + ky) * RR) + u) * CO + o];
        Hr[p] = h.x;
        Hi[p] = h.y;
    }
    __syncthreads();

    int vg = tid >> 3, og = tid & 7;
    int v0 = vg * 8, o0 = og * 8;

    unsigned long long acc[4][8];
#pragma unroll
    for (int k = 0; k < 8; k++) {
        unsigned long long bb = pack2(br[o0 + k], br[o0 + k]);
#pragma unroll
        for (int p = 0; p < 4; p++) acc[p][k] = bb;
    }

    // Residual GEMM: acc[p][k] over v-pairs (v0+2p, v0+2p+1) x o (o0+k)
    const float* xb = Xs + v0 * 65;
#pragma unroll 4
    for (int c = 0; c < CI; c++) {
        unsigned long long xp0 = pack2(xb[c], xb[65 + c]);
        unsigned long long xp1 = pack2(xb[130 + c], xb[195 + c]);
        unsigned long long xp2 = pack2(xb[260 + c], xb[325 + c]);
        unsigned long long xp3 = pack2(xb[390 + c], xb[455 + c]);
        const float* wr = Ws + c * 64 + o0;
        float4 wa = *(const float4*)wr;
        float4 wb = *(const float4*)(wr + 4);
        float wv[8] = {wa.x, wa.y, wa.z, wa.w, wb.x, wb.y, wb.z, wb.w};
#pragma unroll
        for (int k = 0; k < 8; k++) {
            unsigned long long wd = pack2(wv[k], wv[k]);
            acc[0][k] = fma2(xp0, wd, acc[0][k]);
            acc[1][k] = fma2(xp1, wd, acc[1][k]);
            acc[2][k] = fma2(xp2, wd, acc[2][k]);
            acc[3][k] = fma2(xp3, wd, acc[3][k]);
        }
    }

    // Spectral ky = 0 term: + Re(H0[o]) (DC imag discarded, matches irfft)
#pragma unroll
    for (int k = 0; k < 8; k++) {
        unsigned long long h0 = pack2(Hr[o0 + k], Hr[o0 + k]);
#pragma unroll
        for (int p = 0; p < 4; p++) acc[p][k] = add2(acc[p][k], h0);
    }

    // Spectral ky = 1..15: + 2*(Hr*cos - Hi*sin)
    for (int ky = 1; ky < MD; ky++) {
        unsigned long long cp[4], sp[4];
#pragma unroll
        for (int p = 0; p < 4; p++) {
            int ta = (ky * (v0 + 2 * p)) & 255;
            int tb = (ta + ky) & 255;
            cp[p] = pack2(cs2[ta], cs2[tb]);
            sp[p] = pack2(ns2[ta], ns2[tb]);
        }
        const float* hrp = Hr + ky * 64 + o0;
        const float* hip = Hi + ky * 64 + o0;
#pragma unroll
        for (int k = 0; k < 8; k++) {
            unsigned long long hrd = pack2(hrp[k], hrp[k]);
            unsigned long long hid = pack2(hip[k], hip[k]);
#pragma unroll
            for (int p = 0; p < 4; p++) {
                acc[p][k] = fma2(hrd, cp[p], acc[p][k]);
                acc[p][k] = fma2(hid, sp[p], acc[p][k]);
            }
        }
    }

    // SiLU + store (float4)
    float* ob = out + (((size_t)(b * RR + u) * RR) + v0) * CO + o0;
#pragma unroll
    for (int p = 0; p < 4; p++) {
        float lo[8], hi[8];
#pragma unroll
        for (int k = 0; k < 8; k++) unpack2(acc[p][k], lo[k], hi[k]);
        float* r0 = ob + (size_t)(2 * p) * CO;
        float* r1 = ob + (size_t)(2 * p + 1) * CO;
        float4 a0 = make_float4(silu_f(lo[0]), silu_f(lo[1]), silu_f(lo[2]), silu_f(lo[3]));
        float4 a1 = make_float4(silu_f(lo[4]), silu_f(lo[5]), silu_f(lo[6]), silu_f(lo[7]));
        float4 b0 = make_float4(silu_f(hi[0]), silu_f(hi[1]), silu_f(hi[2]), silu_f(hi[3]));
        float4 b1 = make_float4(silu_f(hi[4]), silu_f(hi[5]), silu_f(hi[6]), silu_f(hi[7]));
        *(float4*)r0 = a0;
        *(float4*)(r0 + 4) = a1;
        *(float4*)r1 = b0;
        *(float4*)(r1 + 4) = b1;
    }
}

// ---------------------------------------------------------------------------
// Launcher
// ---------------------------------------------------------------------------
extern "C" void kernel_launch(void* const* d_in, const int* in_sizes, int n_in,
                              void* d_out, int out_size) {
    const float* X = (const float*)d_in[0];
    const float* Wres = (const float*)d_in[1];
    const float* bres = (const float*)d_in[2];
    const float* fw0 = (const float*)d_in[3];
    const float* fw1 = (const float*)d_in[4];
    float* out = (float*)d_out;

    cudaFuncSetAttribute(k5_final, cudaFuncAttributeMaxDynamicSharedMemorySize,
                         SM5_TOT * (int)sizeof(float));

    k1_coldft<<<dim3(RR, NB), 256>>>(X);
    k2_rowdft<<<dim3(MD, NB, 2), 256>>>();
    k3_mix<<<dim3(KXN, MD), 256>>>(fw0, fw1);
    k4_invrow<<<dim3(MD, NB, 4), 256>>>();
    k5_final<<<dim3(RR, NB), 256, SM5_TOT * (int)sizeof(float)>>>(X, Wres, bres, out);
}

// round 7
// speedup vs baseline: 1.2599x; 1.0552x over previous
#include <cuda_runtime.h>
#include <cstdint>

// Problem constants
#define NB 8
#define RR 256
#define CI 64
#define CO 64
#define MD 16
#define KXN 32  // 16 top + 16 bottom kx modes

typedef unsigned long long u64;

// ---------------------------------------------------------------------------
// Scratch (device globals -- no allocation allowed)
// ---------------------------------------------------------------------------
__device__ float2 g_A[NB * MD * RR * CI];   // [b][ky][u][i]   16.8 MB
__device__ float2 g_F[NB * KXN * MD * CI];  // [b][kx][ky][i]   2.1 MB
__device__ float2 g_G[NB * KXN * MD * CO];  // [b][kx][ky][o]   2.1 MB
__device__ float2 g_H[NB * MD * RR * CO];   // [b][ky][u][o]   16.8 MB

// ---------------------------------------------------------------------------
// Packed f32x2 helpers (Blackwell dual-FP32 pipe; only reachable via PTX)
// ---------------------------------------------------------------------------
__device__ __forceinline__ u64 pack2(float lo, float hi) {
    u64 r;
    asm("mov.b64 %0, {%1,%2};" : "=l"(r) : "f"(lo), "f"(hi));
    return r;
}
__device__ __forceinline__ u64 fma2(u64 a, u64 b, u64 c) {
    u64 r;
    asm("fma.rn.f32x2 %0, %1, %2, %3;" : "=l"(r) : "l"(a), "l"(b), "l"(c));
    return r;
}
__device__ __forceinline__ u64 add2(u64 a, u64 b) {
    u64 r;
    asm("add.rn.f32x2 %0, %1, %2;" : "=l"(r) : "l"(a), "l"(b));
    return r;
}
__device__ __forceinline__ void unpack2(u64 v, float& lo, float& hi) {
    asm("mov.b64 {%0,%1}, %2;" : "=f"(lo), "=f"(hi) : "l"(v));
}

__device__ __forceinline__ float silu_f(float x) {
    float e = __expf(-x);
    return __fdividef(x, 1.0f + e);
}

// ---------------------------------------------------------------------------
// K1: partial column DFT along v for ky = 0..15.
// A[b][ky][u][i] = sum_v X[b,u,v,i] * exp(-2*pi*i*ky*v/256)
// v <-> 256-v symmetry. Channel pairs loaded directly as LDG.64 (no packing,
// no smem staging). Thread: lane (tid&31) = channel pair, g (tid>>5) = ky
// pair {2g, 2g+1}. Twiddles in dup'd smem tables, broadcast LDS.64.
// ---------------------------------------------------------------------------
__global__ __launch_bounds__(256) void k1_coldft(const float* __restrict__ X) {
    __shared__ u64 csd[256];  // (c, c)
    __shared__ u64 snd[256];  // (-s, -s)
    int tid = threadIdx.x;
    {
        float s, c;
        sincospif((float)tid * (1.0f / 128.0f), &s, &c);  // angle 2*pi*tid/256
        csd[tid] = pack2(c, c);
        snd[tid] = pack2(-s, -s);
    }
    __syncthreads();

    int u = blockIdx.x, b = blockIdx.y;
    int lane = tid & 31, g = tid >> 5;
    int ky0 = 2 * g, ky1 = 2 * g + 1;
    const u64* xr = (const u64*)(X + ((size_t)(b * RR + u) * RR) * CI) + lane;

    u64 one = pack2(1.0f, 1.0f), mone = pack2(-1.0f, -1.0f);
    u64 x0 = xr[0];
    u64 x128 = xr[128 * 32];
    u64 ar0 = fma2(x128, one, x0);   // ky even: x0 + x128
    u64 ar1 = fma2(x128, mone, x0);  // ky odd:  x0 - x128
    u64 ai0 = pack2(0.0f, 0.0f), ai1 = ai0;

    int t0 = 0, t1 = 0;
#pragma unroll 4
    for (int v = 1; v <= 127; ++v) {
        u64 xa = xr[v * 32];
        u64 xb = xr[(256 - v) * 32];
        u64 smv = add2(xa, xb);
        u64 dfv = fma2(xb, mone, xa);
        t0 = (t0 + ky0) & 255;  // ky0 * v
        t1 = (t1 + ky1) & 255;  // ky1 * v
        ar0 = fma2(smv, csd[t0], ar0);
        ai0 = fma2(dfv, snd[t0], ai0);
        ar1 = fma2(smv, csd[t1], ar1);
        ai1 = fma2(dfv, snd[t1], ai1);
    }

    float4* a4 = (float4*)g_A;
    float rl, rh, il, ih;
    unpack2(ar0, rl, rh); unpack2(ai0, il, ih);
    a4[((size_t)(b * MD + ky0) * RR + u) * 32 + lane] = make_float4(rl, il, rh, ih);
    unpack2(ar1, rl, rh); unpack2(ai1, il, ih);
    a4[((size_t)(b * MD + ky1) * RR + u) * 32 + lane] = make_float4(rl, il, rh, ih);
}

// ---------------------------------------------------------------------------
// K2: partial row DFT along u for kx in {0..15, 240..255}.
// F[b][kxidx][ky][i] = sum_u A[b,ky,u,i] * exp(-2*pi*i*kx*u/256)
// u <-> 256-u symmetry with shared complex sum/diff. (R4 version, verified.)
// ---------------------------------------------------------------------------
__global__ __launch_bounds__(256) void k2_rowdft() {
    __shared__ float cs[256], sn[256];
    int tid = threadIdx.x;
    {
        float s, c;
        sincospif((float)tid * (1.0f / 128.0f), &s, &c);
        cs[tid] = c;
        sn[tid] = s;
    }
    __syncthreads();

    int ky = blockIdx.x, b = blockIdx.y, z = blockIdx.z;
    int i = tid & 63, g = tid >> 6;     // g in 0..3
    int m0 = z * 16 + g * 4;            // this thread's 4 kxidx values
    const float2* ap = g_A + ((size_t)(b * MD + ky) * RR) * CI + i;

    float Fr[4], Fi[4];
    float2 a0 = ap[0];
    float2 a128 = ap[128 * CI];
    int kxv[4];
#pragma unroll
    for (int m = 0; m < 4; m++) {
        int idx = m0 + m;
        kxv[m] = (idx < 16) ? idx : (224 + idx);  // 240..255
        float sgn = (idx & 1) ? -1.0f : 1.0f;
        Fr[m] = a0.x + sgn * a128.x;
        Fi[m] = a0.y + sgn * a128.y;
    }

#pragma unroll 4
    for (int uu = 1; uu <= 127; ++uu) {
        float2 aa = ap[uu * CI];
        float2 ab = ap[(256 - uu) * CI];
        float prs = aa.x + ab.x, mrs = aa.x - ab.x;
        float pis = aa.y + ab.y, mis = aa.y - ab.y;
#pragma unroll
        for (int m = 0; m < 4; m++) {
            int t = (kxv[m] * uu) & 255;
            float c = cs[t], s = sn[t];
            Fr[m] += prs * c + mis * s;
            Fi[m] += pis * c - mrs * s;
        }
    }

#pragma unroll
    for (int m = 0; m < 4; m++) {
        g_F[(((size_t)(b * KXN + m0 + m) * MD) + ky) * CI + i] = make_float2(Fr[m], Fi[m]);
    }
}

// ---------------------------------------------------------------------------
// K3: channel mix (complex einsum over input channels) + ortho-norm fold.
// G[b][kxidx][ky][o] = (1/65536) * sum_i F[b][kxidx][ky][i] * W[i][o]
// ---------------------------------------------------------------------------
__global__ __launch_bounds__(256) void k3_mix(const float* __restrict__ fw0,
                                              const float* __restrict__ fw1) {
    __shared__ float2 ws[CI * CO];   // 32 KB
    __shared__ float2 fs[NB][CI];    // 4 KB
    int tid = threadIdx.x;
    int kxi = blockIdx.x, ky = blockIdx.y;
    const float* src = (kxi < 16) ? fw0 : fw1;
    int x = (kxi < 16) ? kxi : (kxi - 16);

    for (int p = tid; p < CI * CO; p += 256) {
        int i = p >> 6, o = p & 63;
        ws[p] = *(const float2*)(src + ((((size_t)i * CO + o) * MD + x) * MD + ky) * 2);
    }
    for (int p = tid; p < NB * CI; p += 256) {
        int bb = p >> 6, i = p & 63;
        fs[bb][i] = g_F[(((size_t)(bb * KXN + kxi) * MD) + ky) * CI + i];
    }
    __syncthreads();

    int o = tid & 63, bg = tid >> 6;
    const float scale = 1.0f / 65536.0f;  // ortho norm (1/256 fwd * 1/256 inv)
    for (int bb = bg; bb < NB; bb += 4) {
        float Gr = 0.f, Gi = 0.f;
#pragma unroll 8
        for (int i = 0; i < CI; i++) {
            float2 f = fs[bb][i];
            float2 w = ws[i * CO + o];
            Gr += f.x * w.x - f.y * w.y;
            Gi += f.x * w.y + f.y * w.x;
        }
        g_G[(((size_t)(bb * KXN + kxi) * MD) + ky) * CO + o] =
            make_float2(Gr * scale, Gi * scale);
    }
}

// ---------------------------------------------------------------------------
// K4: inverse DFT along kx (32 modes -> 256 u).
// H[b][ky][u][o] = sum_kxidx G[b][kxidx][ky][o] * exp(+2*pi*i*kx*u/256)
// z-split x4 (512 blocks, 16 u/thread). Interleaved (c,s) twiddle table:
// one broadcast LDS.64 per mode instead of two scalar LDS.
// ---------------------------------------------------------------------------
__global__ __launch_bounds__(256) void k4_invrow() {
    __shared__ float2 tw[256];      // (cos, sin)
    __shared__ float2 gs[KXN][CO];  // 16 KB
    int tid = threadIdx.x;
    {
        float s, c;
        sincospif((float)tid * (1.0f / 128.0f), &s, &c);
        tw[tid] = make_float2(c, s);
    }
    int ky = blockIdx.x, b = blockIdx.y;
    for (int p = tid; p < KXN * CO; p += 256) {
        int idx = p >> 6, o = p & 63;
        gs[idx][o] = g_G[(((size_t)(b * KXN + idx) * MD) + ky) * CO + o];
    }
    __syncthreads();

    int o = tid & 63, ug = tid >> 6;
    int ubase = blockIdx.z * 64 + ug * 16;

    for (int uu = 0; uu < 16; ++uu) {
        int u = ubase + uu;
        float Hrv = 0.f, Hiv = 0.f;
        int du = u & 255;
        int t = 0;  // kx = 0..15: t = kx*u mod 256
#pragma unroll
        for (int idx = 0; idx < 16; idx++) {
            float2 g2 = gs[idx][o];
            float2 w = tw[t];
            Hrv += g2.x * w.x - g2.y * w.y;
            Hiv += g2.x * w.y + g2.y * w.x;
            t = (t + du) & 255;
        }
        t = (240 * u) & 255;  // kx = 240..255
#pragma unroll
        for (int idx = 16; idx < 32; idx++) {
            float2 g2 = gs[idx][o];
            float2 w = tw[t];
            Hrv += g2.x * w.x - g2.y * w.y;
            Hiv += g2.x * w.y + g2.y * w.x;
            t = (t + du) & 255;
        }
        g_H[(((size_t)(b * MD + ky) * RR) + u) * CO + o] = make_float2(Hrv, Hiv);
    }
}

// ---------------------------------------------------------------------------
// K5: fused inverse real-DFT along ky (Hermitian, irfft semantics: DC imag
// discarded) + residual GEMM (X @ W_res + b_res) + SiLU.
// Packed f32x2, 8v x 8o tiles. Xs stored PRE-PAIRED (u64 per v-pair) so the
// GEMM inner loop does 4 broadcast LDS.64 instead of 8 scalar LDS + 4 packs.
// Shared: Xpair[128*67] u64 | then floats: Hr[1024] Hi[1024] cs2 ns2 Ws br
// ---------------------------------------------------------------------------
#define XP_STRIDE 67
#define F_BASE (128 * XP_STRIDE * 2)         // float index 17152
#define SM5_HR F_BASE
#define SM5_HI (SM5_HR + MD * CO)
#define SM5_CS (SM5_HI + MD * CO)
#define SM5_NS (SM5_CS + 256)
#define SM5_WS (SM5_NS + 256)
#define SM5_BR (SM5_WS + 4096)
#define SM5_TOT (SM5_BR + 64)                // 23872 floats = 95488 bytes

__global__ __launch_bounds__(256, 2) void k5_final(const float* __restrict__ X,
                                                   const float* __restrict__ Wres,
                                                   const float* __restrict__ bres,
                                                   float* __restrict__ out) {
    extern __shared__ float sm[];
    u64* Xp = (u64*)sm;
    float* Hr = sm + SM5_HR;
    float* Hi = sm + SM5_HI;
    float* cs2 = sm + SM5_CS;
    float* ns2 = sm + SM5_NS;
    float* Ws = sm + SM5_WS;
    float* br = sm + SM5_BR;

    int tid = threadIdx.x;
    int u = blockIdx.x, b = blockIdx.y;

    {
        float s, c;
        sincospif((float)tid * (1.0f / 128.0f), &s, &c);
        cs2[tid] = 2.0f * c;   // factor 2 folded (Hermitian pairs)
        ns2[tid] = -2.0f * s;
    }
    if (tid < 64) br[tid] = bres[tid];
    {
        const float4* w4 = (const float4*)Wres;
        float4* ws4 = (float4*)Ws;
        for (int p = tid; p < 1024; p += 256) ws4[p] = w4[p];
    }
    {
        // Xpair[vp][c] = (X[2vp][c], X[2vp+1][c]) as u64, stride XP_STRIDE.
        const float4* x4 = (const float4*)(X + ((size_t)(b * RR + u) * RR) * CI);
        for (int p = tid; p < 4096; p += 256) {
            float4 xv = x4[p];
            int v = p >> 4;            // 16 float4 per v-row
            int cq = (p & 15) * 4;
            float* base = (float*)(Xp + (size_t)(v >> 1) * XP_STRIDE + cq) + (v & 1);
            base[0] = xv.x; base[2] = xv.y; base[4] = xv.z; base[6] = xv.w;
        }
    }
    for (int p = tid; p < MD * CO; p += 256) {
        int ky = p >> 6, o = p & 63;
        float2 h = g_H[(((size_t)(b * MD + ky) * RR) + u) * CO + o];
        Hr[p] = h.x;
        Hi[p] = h.y;
    }
    __syncthreads();

    int vg = tid >> 3, og = tid & 7;
    int v0 = vg * 8, o0 = og * 8;
    int vp0 = vg * 4;

    unsigned long long acc[4][8];
#pragma unroll
    for (int k = 0; k < 8; k++) {
        u64 bb = pack2(br[o0 + k], br[o0 + k]);
#pragma unroll
        for (int p = 0; p < 4; p++) acc[p][k] = bb;
    }

    // Residual GEMM: acc[p][k] over v-pair (vp0+p) x o (o0+k)
    const u64* xb = Xp + (size_t)vp0 * XP_STRIDE;
#pragma unroll 4
    for (int c = 0; c < CI; c++) {
        u64 xp0 = xb[c];
        u64 xp1 = xb[XP_STRIDE + c];
        u64 xp2 = xb[2 * XP_STRIDE + c];
        u64 xp3 = xb[3 * XP_STRIDE + c];
        const float* wr = Ws + c * 64 + o0;
        float4 wa = *(const float4*)wr;
        float4 wb = *(const float4*)(wr + 4);
        float wv[8] = {wa.x, wa.y, wa.z, wa.w, wb.x, wb.y, wb.z, wb.w};
#pragma unroll
        for (int k = 0; k < 8; k++) {
            u64 wd = pack2(wv[k], wv[k]);
            acc[0][k] = fma2(xp0, wd, acc[0][k]);
            acc[1][k] = fma2(xp1, wd, acc[1][k]);
            acc[2][k] = fma2(xp2, wd, acc[2][k]);
            acc[3][k] = fma2(xp3, wd, acc[3][k]);
        }
    }

    // Spectral ky = 0 term: + Re(H0[o]) (DC imag discarded, matches irfft)
#pragma unroll
    for (int k = 0; k < 8; k++) {
        u64 h0 = pack2(Hr[o0 + k], Hr[o0 + k]);
#pragma unroll
        for (int p = 0; p < 4; p++) acc[p][k] = add2(acc[p][k], h0);
    }

    // Spectral ky = 1..15: + 2*(Hr*cos - Hi*sin)
    for (int ky = 1; ky < MD; ky++) {
        u64 cp[4], sp[4];
#pragma unroll
        for (int p = 0; p < 4; p++) {
            int ta = (ky * (v0 + 2 * p)) & 255;
            int tb = (ta + ky) & 255;
            cp[p] = pack2(cs2[ta], cs2[tb]);
            sp[p] = pack2(ns2[ta], ns2[tb]);
        }
        const float* hrp = Hr + ky * 64 + o0;
        const float* hip = Hi + ky * 64 + o0;
#pragma unroll
        for (int k = 0; k < 8; k++) {
            u64 hrd = pack2(hrp[k], hrp[k]);
            u64 hid = pack2(hip[k], hip[k]);
#pragma unroll
            for (int p = 0; p < 4; p++) {
                acc[p][k] = fma2(hrd, cp[p], acc[p][k]);
                acc[p][k] = fma2(hid, sp[p], acc[p][k]);
            }
        }
    }

    // SiLU + store (float4)
    float* ob = out + (((size_t)(b * RR + u) * RR) + v0) * CO + o0;
#pragma unroll
    for (int p = 0; p < 4; p++) {
        float lo[8], hi[8];
#pragma unroll
        for (int k = 0; k < 8; k++) unpack2(acc[p][k], lo[k], hi[k]);
        float* r0 = ob + (size_t)(2 * p) * CO;
        float* r1 = ob + (size_t)(2 * p + 1) * CO;
        *(float4*)r0 = make_float4(silu_f(lo[0]), silu_f(lo[1]), silu_f(lo[2]), silu_f(lo[3]));
        *(float4*)(r0 + 4) = make_float4(silu_f(lo[4]), silu_f(lo[5]), silu_f(lo[6]), silu_f(lo[7]));
        *(float4*)r1 = make_float4(silu_f(hi[0]), silu_f(hi[1]), silu_f(hi[2]), silu_f(hi[3]));
        *(float4*)(r1 + 4) = make_float4(silu_f(hi[4]), silu_f(hi[5]), silu_f(hi[6]), silu_f(hi[7]));
    }
}

// ---------------------------------------------------------------------------
// Launcher
// ---------------------------------------------------------------------------
extern "C" void kernel_launch(void* const* d_in, const int* in_sizes, int n_in,
                              void* d_out, int out_size) {
    const float* X = (const float*)d_in[0];
    const float* Wres = (const float*)d_in[1];
    const float* bres = (const float*)d_in[2];
    const float* fw0 = (const float*)d_in[3];
    const float* fw1 = (const float*)d_in[4];
    float* out = (float*)d_out;

    cudaFuncSetAttribute(k5_final, cudaFuncAttributeMaxDynamicSharedMemorySize,
                         SM5_TOT * (int)sizeof(float));

    k1_coldft<<<dim3(RR, NB), 256>>>(X);
    k2_rowdft<<<dim3(MD, NB, 2), 256>>>();
    k3_mix<<<dim3(KXN, MD), 256>>>(fw0, fw1);
    k4_invrow<<<dim3(MD, NB, 4), 256>>>();
    k5_final<<<dim3(RR, NB), 256, SM5_TOT * (int)sizeof(float)>>>(X, Wres, bres, out);
}